// round 10
// baseline (speedup 1.0000x reference)
#include <cuda_runtime.h>
#include <cuda_bf16.h>

#define EPS_SIGN 1e-8f
#define EPS_NORM 1e-9f

// Padded xyz as float4: each node gather = ONE LDG.128.
#define XYZ4_CAP 131072
__device__ float4 g_xyz4[XYZ4_CAP];

// Vectorized repack: thread j handles nodes 4j..4j+3 via 3 float4 loads.
__global__ __launch_bounds__(256)
void repack_xyz4_kernel(const float4* __restrict__ xyz4, int N4, int N)
{
    int j = blockIdx.x * blockDim.x + threadIdx.x;
    if (j < N4) {
        float4 f0 = xyz4[3*j + 0];   // x0 y0 z0 x1
        float4 f1 = xyz4[3*j + 1];   // y1 z1 x2 y2
        float4 f2 = xyz4[3*j + 2];   // z2 x3 y3 z3
        g_xyz4[4*j + 0] = make_float4(f0.x, f0.y, f0.z, 0.0f);
        g_xyz4[4*j + 1] = make_float4(f0.w, f1.x, f1.y, 0.0f);
        g_xyz4[4*j + 2] = make_float4(f1.z, f1.w, f2.x, 0.0f);
        g_xyz4[4*j + 3] = make_float4(f2.y, f2.z, f2.w, 0.0f);
    } else if (j == N4) {
        const float* xyz = (const float*)xyz4;
        for (int i = 4 * N4; i < N; i++)
            g_xyz4[i] = make_float4(xyz[3*i+0], xyz[3*i+1], xyz[3*i+2], 0.0f);
    }
}

__device__ __forceinline__ void edge_math(float4 a, float4 b,
                                          float cx, float cy, float cz,
                                          float& vx, float& vy, float& vz,
                                          float& dis)
{
    float dx = a.x - b.x, dy = a.y - b.y, dz = a.z - b.z;
    float ax = fabsf(dx), ay = fabsf(dy), az = fabsf(dz);

    float mx = fminf(cx - ax, ax);
    float my = fminf(cy - ay, ay);
    float mz = fminf(cz - az, az);

    float k2x = (fabsf(mx) == ax) ? 1.0f : -1.0f;
    float k2y = (fabsf(my) == ay) ? 1.0f : -1.0f;
    float k2z = (fabsf(mz) == az) ? 1.0f : -1.0f;

    float sx = (dx + EPS_SIGN >= 0.0f) ? 1.0f : -1.0f;
    float sy = (dy + EPS_SIGN >= 0.0f) ? 1.0f : -1.0f;
    float sz = (dz + EPS_SIGN >= 0.0f) ? 1.0f : -1.0f;

    vx = mx * (k2x * sx);
    vy = my * (k2y * sy);
    vz = mz * (k2z * sz);

    float ex = dx + EPS_NORM, ey = dy + EPS_NORM, ez = dz + EPS_NORM;
    dis = sqrtf(ex*ex + ey*ey + ez*ez);
}

// 4 edges/thread, warp-strided (e, e+32, e+64, e+96):
//  - all 8 gather LDG.128s front-batched -> deep MLP, l1tex stays saturated
//  - dis stores coalesced per slot (4 wf / 128 edges)
//  - vec via shuffle-coalesced passes (12 wf / 128 edges = floor)
__global__ __launch_bounds__(256)
void edge_min_image_kernel(const int*   __restrict__ src,
                           const int*   __restrict__ dst,
                           const float* __restrict__ cell,
                           float* __restrict__ out_dis,
                           float* __restrict__ out_vec,
                           int E)
{
    int tid  = blockIdx.x * blockDim.x + threadIdx.x;
    int lane = threadIdx.x & 31;
    int base = ((tid >> 5) << 7);        // 128 edges per warp
    if (base >= E) return;

    const float cx = __ldg(&cell[0]);
    const float cy = __ldg(&cell[1]);
    const float cz = __ldg(&cell[2]);

    if (base + 128 <= E) {
        int e0 = base + lane;

        // ---- front-batch all loads: 8 index LDGs then 8 gather LDG.128s ----
        int s0 = __ldg(&src[e0     ]);
        int s1 = __ldg(&src[e0 + 32]);
        int s2 = __ldg(&src[e0 + 64]);
        int s3 = __ldg(&src[e0 + 96]);
        int d0 = __ldg(&dst[e0     ]);
        int d1 = __ldg(&dst[e0 + 32]);
        int d2 = __ldg(&dst[e0 + 64]);
        int d3 = __ldg(&dst[e0 + 96]);

        float4 a0 = g_xyz4[s0];
        float4 a1 = g_xyz4[s1];
        float4 a2 = g_xyz4[s2];
        float4 a3 = g_xyz4[s3];
        float4 b0 = g_xyz4[d0];
        float4 b1 = g_xyz4[d1];
        float4 b2 = g_xyz4[d2];
        float4 b3 = g_xyz4[d3];

        float vx[4], vy[4], vz[4], dis[4];
        edge_math(a0, b0, cx, cy, cz, vx[0], vy[0], vz[0], dis[0]);
        edge_math(a1, b1, cx, cy, cz, vx[1], vy[1], vz[1], dis[1]);
        edge_math(a2, b2, cx, cy, cz, vx[2], vy[2], vz[2], dis[2]);
        edge_math(a3, b3, cx, cy, cz, vx[3], vy[3], vz[3], dis[3]);

        out_dis[e0     ] = dis[0];
        out_dis[e0 + 32] = dis[1];
        out_dis[e0 + 64] = dis[2];
        out_dis[e0 + 96] = dis[3];

        // vec span: out_vec[3*base .. +384). Slot q owns floats [96q, 96q+96),
        // 3 coalesced passes per slot.
        float* bp = out_vec + 3 * base;
        #pragma unroll
        for (int q = 0; q < 4; q++) {
            #pragma unroll
            for (int p = 0; p < 3; p++) {
                int g  = p * 32 + lane;      // 0..95 within slot-q span
                int sl = g / 3;              // owning lane
                int c  = g - 3 * sl;         // component
                float t0 = __shfl_sync(0xffffffffu, vx[q], sl);
                float t1 = __shfl_sync(0xffffffffu, vy[q], sl);
                float t2 = __shfl_sync(0xffffffffu, vz[q], sl);
                bp[96 * q + g] = (c == 0) ? t0 : ((c == 1) ? t1 : t2);
            }
        }
    } else {
        // ---- tail warp: per-edge scalar ----
        for (int k = 0; k < 4; k++) {
            int e = base + 32 * k + lane;
            if (e < E) {
                float4 a = g_xyz4[__ldg(&src[e])];
                float4 b = g_xyz4[__ldg(&dst[e])];
                float vx, vy, vz, dis;
                edge_math(a, b, cx, cy, cz, vx, vy, vz, dis);
                out_dis[e] = dis;
                float* vp = out_vec + 3 * e;
                vp[0] = vx; vp[1] = vy; vp[2] = vz;
            }
        }
    }
}

// Fallback (N > scratch capacity): scalar-gather path, always correct.
__global__ __launch_bounds__(256)
void edge_min_image_fallback(const float* __restrict__ xyz,
                             const int*   __restrict__ src,
                             const int*   __restrict__ dst,
                             const float* __restrict__ cell,
                             float* __restrict__ out_dis,
                             float* __restrict__ out_vec,
                             int E)
{
    const float cx = __ldg(&cell[0]);
    const float cy = __ldg(&cell[1]);
    const float cz = __ldg(&cell[2]);

    int e = blockIdx.x * blockDim.x + threadIdx.x;
    if (e >= E) return;

    int si = src[e], di = dst[e];
    float dx = xyz[3*si+0] - xyz[3*di+0];
    float dy = xyz[3*si+1] - xyz[3*di+1];
    float dz = xyz[3*si+2] - xyz[3*di+2];

    float ax = fabsf(dx), ay = fabsf(dy), az = fabsf(dz);
    float mx = fminf(cx - ax, ax);
    float my = fminf(cy - ay, ay);
    float mz = fminf(cz - az, az);
    float k2x = (fabsf(mx) == ax) ? 1.0f : -1.0f;
    float k2y = (fabsf(my) == ay) ? 1.0f : -1.0f;
    float k2z = (fabsf(mz) == az) ? 1.0f : -1.0f;
    float sx = (dx + EPS_SIGN >= 0.0f) ? 1.0f : -1.0f;
    float sy = (dy + EPS_SIGN >= 0.0f) ? 1.0f : -1.0f;
    float sz = (dz + EPS_SIGN >= 0.0f) ? 1.0f : -1.0f;

    out_vec[3*e+0] = mx * (k2x * sx);
    out_vec[3*e+1] = my * (k2y * sy);
    out_vec[3*e+2] = mz * (k2z * sz);

    float ex = dx + EPS_NORM, ey = dy + EPS_NORM, ez = dz + EPS_NORM;
    out_dis[e] = sqrtf(ex*ex + ey*ey + ez*ez);
}

extern "C" void kernel_launch(void* const* d_in, const int* in_sizes, int n_in,
                              void* d_out, int out_size)
{
    const float* xyz  = (const float*)d_in[0];
    const int*   src  = (const int*)  d_in[1];
    const int*   dst  = (const int*)  d_in[2];
    const float* cell = (const float*)d_in[3];

    int N = in_sizes[0] / 3;   // xyz rows
    int E = in_sizes[1];       // number of edges

    float* out_dis = (float*)d_out;   // [E]
    float* out_vec = out_dis + E;     // [E,3] row-major

    const int t = 256;
    if (N <= XYZ4_CAP) {
        int N4 = N / 4;
        int rthreads = N4 + 1;
        repack_xyz4_kernel<<<(rthreads + t - 1) / t, t>>>(
            (const float4*)xyz, N4, N);
        // 128 edges per warp, 8 warps per block
        int warps  = (E + 127) / 128;
        int blocks = (warps + 7) / 8;
        edge_min_image_kernel<<<blocks, t>>>(src, dst, cell,
                                             out_dis, out_vec, E);
    } else {
        edge_min_image_fallback<<<(E + t - 1) / t, t>>>(xyz, src, dst, cell,
                                                        out_dis, out_vec, E);
    }
}

// round 11
// speedup vs baseline: 1.0252x; 1.0252x over previous
#include <cuda_runtime.h>
#include <cuda_bf16.h>

#define EPS_SIGN 1e-8f
#define EPS_NORM 1e-9f

// Padded xyz as float4: each node gather = ONE LDG.128.
#define XYZ4_CAP 131072
__device__ float4 g_xyz4[XYZ4_CAP];

// Vectorized repack: thread j handles nodes 4j..4j+3 via 3 float4 loads.
__global__ __launch_bounds__(256)
void repack_xyz4_kernel(const float4* __restrict__ xyz4, int N4, int N)
{
    int j = blockIdx.x * blockDim.x + threadIdx.x;
    if (j < N4) {
        float4 f0 = xyz4[3*j + 0];   // x0 y0 z0 x1
        float4 f1 = xyz4[3*j + 1];   // y1 z1 x2 y2
        float4 f2 = xyz4[3*j + 2];   // z2 x3 y3 z3
        g_xyz4[4*j + 0] = make_float4(f0.x, f0.y, f0.z, 0.0f);
        g_xyz4[4*j + 1] = make_float4(f0.w, f1.x, f1.y, 0.0f);
        g_xyz4[4*j + 2] = make_float4(f1.z, f1.w, f2.x, 0.0f);
        g_xyz4[4*j + 3] = make_float4(f2.y, f2.z, f2.w, 0.0f);
    } else if (j == N4) {
        const float* xyz = (const float*)xyz4;
        for (int i = 4 * N4; i < N; i++)
            g_xyz4[i] = make_float4(xyz[3*i+0], xyz[3*i+1], xyz[3*i+2], 0.0f);
    }
}

// Half-warp-split gather: two complementary-predicated LDG.128s so each
// instruction touches ~16 distinct lines instead of ~32, converting
// within-LDG replay wavefronts (2.07 cyc) into cross-LDG ones (1.0 cyc).
// Inline PTX keeps ptxas from re-merging the pair.
__device__ __forceinline__ float4 gather_split(int idx, int lane)
{
    const float4* addr = g_xyz4 + idx;
    float4 r;
    asm volatile(
        "{\n\t"
        ".reg .pred lp;\n\t"
        "setp.lt.s32 lp, %4, 16;\n\t"
        "@lp  ld.global.nc.v4.f32 {%0,%1,%2,%3}, [%5];\n\t"
        "@!lp ld.global.nc.v4.f32 {%0,%1,%2,%3}, [%5];\n\t"
        "}"
        : "=f"(r.x), "=f"(r.y), "=f"(r.z), "=f"(r.w)
        : "r"(lane), "l"(addr));
    return r;
}

__device__ __forceinline__ void edge_math(float4 a, float4 b,
                                          float cx, float cy, float cz,
                                          float& vx, float& vy, float& vz,
                                          float& dis)
{
    float dx = a.x - b.x, dy = a.y - b.y, dz = a.z - b.z;
    float ax = fabsf(dx), ay = fabsf(dy), az = fabsf(dz);

    float mx = fminf(cx - ax, ax);
    float my = fminf(cy - ay, ay);
    float mz = fminf(cz - az, az);

    float k2x = (fabsf(mx) == ax) ? 1.0f : -1.0f;
    float k2y = (fabsf(my) == ay) ? 1.0f : -1.0f;
    float k2z = (fabsf(mz) == az) ? 1.0f : -1.0f;

    float sx = (dx + EPS_SIGN >= 0.0f) ? 1.0f : -1.0f;
    float sy = (dy + EPS_SIGN >= 0.0f) ? 1.0f : -1.0f;
    float sz = (dz + EPS_SIGN >= 0.0f) ? 1.0f : -1.0f;

    vx = mx * (k2x * sx);
    vy = my * (k2y * sy);
    vz = mz * (k2z * sz);

    float ex = dx + EPS_NORM, ey = dy + EPS_NORM, ez = dz + EPS_NORM;
    dis = sqrtf(ex*ex + ey*ey + ez*ez);
}

// R6 geometry (best measured): 2 edges/thread warp-strided (e, e+32),
// shuffle-coalesced vec stores (3 wf per 32 edges), + split gathers.
__global__ __launch_bounds__(256)
void edge_min_image_kernel(const int*   __restrict__ src,
                           const int*   __restrict__ dst,
                           const float* __restrict__ cell,
                           float* __restrict__ out_dis,
                           float* __restrict__ out_vec,
                           int E)
{
    int tid  = blockIdx.x * blockDim.x + threadIdx.x;
    int lane = threadIdx.x & 31;
    int base = ((tid >> 5) << 6);        // 64 edges per warp
    if (base >= E) return;

    const float cx = __ldg(&cell[0]);
    const float cy = __ldg(&cell[1]);
    const float cz = __ldg(&cell[2]);

    int e0 = base + lane;
    int e1 = base + 32 + lane;

    if (base + 64 <= E) {
        int s0 = __ldg(&src[e0]);
        int s1 = __ldg(&src[e1]);
        int d0 = __ldg(&dst[e0]);
        int d1 = __ldg(&dst[e1]);

        float4 a0 = gather_split(s0, lane);
        float4 a1 = gather_split(s1, lane);
        float4 b0 = gather_split(d0, lane);
        float4 b1 = gather_split(d1, lane);

        float vx0, vy0, vz0, dis0, vx1, vy1, vz1, dis1;
        edge_math(a0, b0, cx, cy, cz, vx0, vy0, vz0, dis0);
        edge_math(a1, b1, cx, cy, cz, vx1, vy1, vz1, dis1);

        out_dis[e0] = dis0;
        out_dis[e1] = dis1;

        float* bp = out_vec + 3 * base;  // 192-float span
        #pragma unroll
        for (int p = 0; p < 3; p++) {    // slot 0: floats [0,96)
            int g  = p * 32 + lane;
            int sl = g / 3;
            int c  = g - 3 * sl;
            float t0 = __shfl_sync(0xffffffffu, vx0, sl);
            float t1 = __shfl_sync(0xffffffffu, vy0, sl);
            float t2 = __shfl_sync(0xffffffffu, vz0, sl);
            bp[g] = (c == 0) ? t0 : ((c == 1) ? t1 : t2);
        }
        #pragma unroll
        for (int p = 0; p < 3; p++) {    // slot 1: floats [96,192)
            int g  = p * 32 + lane;
            int sl = g / 3;
            int c  = g - 3 * sl;
            float t0 = __shfl_sync(0xffffffffu, vx1, sl);
            float t1 = __shfl_sync(0xffffffffu, vy1, sl);
            float t2 = __shfl_sync(0xffffffffu, vz1, sl);
            bp[96 + g] = (c == 0) ? t0 : ((c == 1) ? t1 : t2);
        }
    } else {
        // tail warp: per-edge scalar
        #pragma unroll
        for (int k = 0; k < 2; k++) {
            int e = base + 32 * k + lane;
            if (e < E) {
                float4 a = g_xyz4[__ldg(&src[e])];
                float4 b = g_xyz4[__ldg(&dst[e])];
                float vx, vy, vz, dis;
                edge_math(a, b, cx, cy, cz, vx, vy, vz, dis);
                out_dis[e] = dis;
                float* vp = out_vec + 3 * e;
                vp[0] = vx; vp[1] = vy; vp[2] = vz;
            }
        }
    }
}

// Fallback (N > scratch capacity): scalar-gather path, always correct.
__global__ __launch_bounds__(256)
void edge_min_image_fallback(const float* __restrict__ xyz,
                             const int*   __restrict__ src,
                             const int*   __restrict__ dst,
                             const float* __restrict__ cell,
                             float* __restrict__ out_dis,
                             float* __restrict__ out_vec,
                             int E)
{
    const float cx = __ldg(&cell[0]);
    const float cy = __ldg(&cell[1]);
    const float cz = __ldg(&cell[2]);

    int e = blockIdx.x * blockDim.x + threadIdx.x;
    if (e >= E) return;

    int si = src[e], di = dst[e];
    float dx = xyz[3*si+0] - xyz[3*di+0];
    float dy = xyz[3*si+1] - xyz[3*di+1];
    float dz = xyz[3*si+2] - xyz[3*di+2];

    float ax = fabsf(dx), ay = fabsf(dy), az = fabsf(dz);
    float mx = fminf(cx - ax, ax);
    float my = fminf(cy - ay, ay);
    float mz = fminf(cz - az, az);
    float k2x = (fabsf(mx) == ax) ? 1.0f : -1.0f;
    float k2y = (fabsf(my) == ay) ? 1.0f : -1.0f;
    float k2z = (fabsf(mz) == az) ? 1.0f : -1.0f;
    float sx = (dx + EPS_SIGN >= 0.0f) ? 1.0f : -1.0f;
    float sy = (dy + EPS_SIGN >= 0.0f) ? 1.0f : -1.0f;
    float sz = (dz + EPS_SIGN >= 0.0f) ? 1.0f : -1.0f;

    out_vec[3*e+0] = mx * (k2x * sx);
    out_vec[3*e+1] = my * (k2y * sy);
    out_vec[3*e+2] = mz * (k2z * sz);

    float ex = dx + EPS_NORM, ey = dy + EPS_NORM, ez = dz + EPS_NORM;
    out_dis[e] = sqrtf(ex*ex + ey*ey + ez*ez);
}

extern "C" void kernel_launch(void* const* d_in, const int* in_sizes, int n_in,
                              void* d_out, int out_size)
{
    const float* xyz  = (const float*)d_in[0];
    const int*   src  = (const int*)  d_in[1];
    const int*   dst  = (const int*)  d_in[2];
    const float* cell = (const float*)d_in[3];

    int N = in_sizes[0] / 3;   // xyz rows
    int E = in_sizes[1];       // number of edges

    float* out_dis = (float*)d_out;   // [E]
    float* out_vec = out_dis + E;     // [E,3] row-major

    const int t = 256;
    if (N <= XYZ4_CAP) {
        int N4 = N / 4;
        int rthreads = N4 + 1;
        repack_xyz4_kernel<<<(rthreads + t - 1) / t, t>>>(
            (const float4*)xyz, N4, N);
        int warps  = (E + 63) / 64;      // 64 edges per warp
        int blocks = (warps + 7) / 8;    // 8 warps per block
        edge_min_image_kernel<<<blocks, t>>>(src, dst, cell,
                                             out_dis, out_vec, E);
    } else {
        edge_min_image_fallback<<<(E + t - 1) / t, t>>>(xyz, src, dst, cell,
                                                        out_dis, out_vec, E);
    }
}